// round 3
// baseline (speedup 1.0000x reference)
#include <cuda_runtime.h>

#define S 2048
#define C 4096
#define K 4
#define SCHUNK 8   // samples per block

// Thread owns 4 fixed consecutive channels; loops over SCHUNK samples.
// Window lw[k][0..11] = comp[k][c-4 .. c+7] (zero-padded at row edges) lives in
// local memory so the per-sample, per-k tap offset r (warp-uniform) is resolved
// by computed-address LDL instead of shuffles/branches/select trees.
// shift in [-4,4) => mi in [-4,3] => r = mi+4 in [0,7], taps lw[r..r+4] in range.
__global__ void __launch_bounds__(256, 4)
smf_kernel(const float* __restrict__ comp,      // (K, C)
           const float* __restrict__ contrib,   // (S, K)
           const float* __restrict__ shift,     // (S, K)
           float* __restrict__ out)             // (S, C)
{
    const int warp = threadIdx.x >> 5;
    const int lane = threadIdx.x & 31;
    const int c    = blockIdx.x * 1024 + warp * 128 + lane * 4;  // thread's first channel
    const int i4   = c >> 2;
    const int s0   = blockIdx.y * SCHUNK;

    float lw[K][12];   // dynamically indexed -> local memory (lane-interleaved, coalesced)
#pragma unroll
    for (int k = 0; k < K; k++) {
        const float4* c4 = reinterpret_cast<const float4*>(comp + k * C);
        float4 p = (i4 > 0)           ? __ldg(&c4[i4 - 1]) : make_float4(0.f, 0.f, 0.f, 0.f);
        float4 o = __ldg(&c4[i4]);
        float4 n = (i4 < C / 4 - 1)   ? __ldg(&c4[i4 + 1]) : make_float4(0.f, 0.f, 0.f, 0.f);
        lw[k][0] = p.x; lw[k][1]  = p.y; lw[k][2]  = p.z; lw[k][3]  = p.w;
        lw[k][4] = o.x; lw[k][5]  = o.y; lw[k][6]  = o.z; lw[k][7]  = o.w;
        lw[k][8] = n.x; lw[k][9]  = n.y; lw[k][10] = n.z; lw[k][11] = n.w;
    }

    float* obase = out + c;
#pragma unroll 2
    for (int s = s0; s < s0 + SCHUNK; s++) {
        // broadcast loads: whole warp reads the same (S,K) rows
        const float4 sh4 = __ldg(reinterpret_cast<const float4*>(shift + s * K));
        const float4 w4  = __ldg(reinterpret_cast<const float4*>(contrib + s * K));
        const float shs[4] = {sh4.x, sh4.y, sh4.z, sh4.w};
        const float ws[4]  = {w4.x,  w4.y,  w4.z,  w4.w};

        float a0 = 0.f, a1 = 0.f, a2 = 0.f, a3 = 0.f;
#pragma unroll
        for (int k = 0; k < K; k++) {
            const float sh = shs[k];
            const float w  = ws[k];
            const float m  = floorf(sh);
            const float f  = sh - m;
            const float w1 = w * f;
            const float w0 = w - w1;
            int r = (int)m + 4;
            r = max(0, min(7, r));            // safety clamp (keeps LDL in bounds)

            const float h0 = lw[k][r];
            const float h1 = lw[k][r + 1];
            const float h2 = lw[k][r + 2];
            const float h3 = lw[k][r + 3];
            const float h4 = lw[k][r + 4];
            a0 = fmaf(w0, h0, fmaf(w1, h1, a0));
            a1 = fmaf(w0, h1, fmaf(w1, h2, a1));
            a2 = fmaf(w0, h2, fmaf(w1, h3, a2));
            a3 = fmaf(w0, h3, fmaf(w1, h4, a3));
        }
        *reinterpret_cast<float4*>(obase + (size_t)s * C) = make_float4(a0, a1, a2, a3);
    }
}

extern "C" void kernel_launch(void* const* d_in, const int* in_sizes, int n_in,
                              void* d_out, int out_size) {
    // metadata order: inputs (unused), components, contributions, shift
    const float* comp    = (const float*)d_in[1];
    const float* contrib = (const float*)d_in[2];
    const float* shift   = (const float*)d_in[3];
    float*       out     = (float*)d_out;

    dim3 grid(C / 1024, S / SCHUNK);   // (4, 256) = 1024 blocks
    dim3 block(256);
    smf_kernel<<<grid, block>>>(comp, contrib, shift, out);
}